// round 4
// baseline (speedup 1.0000x reference)
#include <cuda_runtime.h>
#include <cuda_bf16.h>
#include <cstdint>

// ============================================================================
// OrthogonalTransform: Y = X @ R, X viewed as (M=524288, 128), R 128x128.
// Baseline-sm_103 path (no tcgen05 on this toolchain target): mma.sync HMMA
// bf16 with 3-pass split (x=hi+lo, R=Rhi+Rlo, D = hi*Rhi + hi*Rlo + lo*Rhi).
// Persistent CTAs; B pre-split+repacked in smem in exact B-fragment layout;
// A loaded GMEM->regs directly in A-fragment layout.
// ============================================================================

#define THREADS 256
// B pack: entry (ks[8], nt[16], hl[2], t[32], ri[2]) u32
// byte offset = (ks*16+nt)*512 + hl*256 + t*8 + ri*4   -> total 64 KB
#define SMEM_BYTES (64 * 1024)

__device__ __forceinline__ void split2(float2 v, uint32_t& hi, uint32_t& lo) {
    __nv_bfloat162 h = __float22bfloat162_rn(v);
    float2 hf = __bfloat1622float2(h);
    __nv_bfloat162 l = __float22bfloat162_rn(make_float2(v.x - hf.x, v.y - hf.y));
    hi = *reinterpret_cast<uint32_t*>(&h);
    lo = *reinterpret_cast<uint32_t*>(&l);
}

__device__ __forceinline__ void mma_bf16(float* d, const uint32_t* a,
                                         uint32_t b0, uint32_t b1) {
    asm volatile(
        "mma.sync.aligned.m16n8k16.row.col.f32.bf16.bf16.f32 "
        "{%0,%1,%2,%3}, {%4,%5,%6,%7}, {%8,%9}, {%0,%1,%2,%3};"
        : "+f"(d[0]), "+f"(d[1]), "+f"(d[2]), "+f"(d[3])
        : "r"(a[0]), "r"(a[1]), "r"(a[2]), "r"(a[3]), "r"(b0), "r"(b1));
}

__global__ void __launch_bounds__(THREADS, 2)
OrthogonalTransform_kernel(const float* __restrict__ x,
                           const float* __restrict__ rot,
                           float* __restrict__ out,
                           int num_tiles) {
    extern __shared__ char smem[];
    uint32_t* bpack = reinterpret_cast<uint32_t*>(smem);

    const int tid = threadIdx.x;
    const int wid = tid >> 5;
    const int lane = tid & 31;

    // ---- Prologue: R -> B = R^T fragments, bf16 hi/lo, packed per-lane ----
    // B operand element (k, n) = R[k][n] = rot[k*128 + n].
    // Fragment (m16n8k16, col): lane holds n = nt*8 + lane/4,
    //   reg ri: k = ks*16 + (lane%4)*2 + ri*8, pair {k, k+1} (low half = k).
    for (int idx = tid; idx < 8192; idx += THREADS) {
        int ri = idx & 1;
        int t  = (idx >> 1) & 31;
        int nt = (idx >> 6) & 15;
        int ks = idx >> 10;
        int n = nt * 8 + (t >> 2);
        int k = ks * 16 + (t & 3) * 2 + ri * 8;
        float2 v = make_float2(rot[k * 128 + n], rot[(k + 1) * 128 + n]);
        uint32_t hi, lo;
        split2(v, hi, lo);
        int u = (ks * 16 + nt) * 128 + t * 2 + ri;  // u32 index, hl=0
        bpack[u]      = hi;
        bpack[u + 64] = lo;                          // hl=1 (+256B)
    }
    __syncthreads();

    // Warp tiling: CTA tile = 128 rows x 128 cols.
    // warp w: rows [32*(w>>1), +32) (2 m16 tiles), cols [64*(w&1), +64) (8 n8 tiles)
    const int mgrp = wid >> 1;
    const int ngrp = wid & 1;
    const int tq = lane >> 2;   // 0..7
    const int tr = lane & 3;    // 0..3

    for (int tile = blockIdx.x; tile < num_tiles; tile += gridDim.x) {
        float acc[2][8][4];
        #pragma unroll
        for (int mi = 0; mi < 2; mi++)
            #pragma unroll
            for (int ni = 0; ni < 8; ni++)
                #pragma unroll
                for (int j = 0; j < 4; j++) acc[mi][ni][j] = 0.0f;

        const float* xt = x + (size_t)tile * 16384;

        #pragma unroll 1
        for (int ks = 0; ks < 8; ks++) {
            // ---- A fragments: GMEM -> regs, split to bf16 hi/lo ----
            uint32_t ahi[2][4], alo[2][4];
            #pragma unroll
            for (int mi = 0; mi < 2; mi++) {
                int r0 = mgrp * 32 + mi * 16 + tq;
                int kc = ks * 16 + tr * 2;
                const float* p = xt + r0 * 128 + kc;
                float2 v0 = *reinterpret_cast<const float2*>(p);             // (r0, kc)
                float2 v1 = *reinterpret_cast<const float2*>(p + 8 * 128);   // (r0+8, kc)
                float2 v2 = *reinterpret_cast<const float2*>(p + 8);         // (r0, kc+8)
                float2 v3 = *reinterpret_cast<const float2*>(p + 8 * 128 + 8);
                split2(v0, ahi[mi][0], alo[mi][0]);
                split2(v1, ahi[mi][1], alo[mi][1]);
                split2(v2, ahi[mi][2], alo[mi][2]);
                split2(v3, ahi[mi][3], alo[mi][3]);
            }

            // ---- B fragments from packed smem + 3-pass HMMA ----
            #pragma unroll
            for (int ni = 0; ni < 8; ni++) {
                int nt = ngrp * 8 + ni;
                const uint32_t* pb = bpack + (ks * 16 + nt) * 128 + lane * 2;
                uint2 h = *reinterpret_cast<const uint2*>(pb);       // hi: ri 0,1
                uint2 l = *reinterpret_cast<const uint2*>(pb + 64);  // lo (+256B)
                #pragma unroll
                for (int mi = 0; mi < 2; mi++) {
                    mma_bf16(acc[mi][ni], ahi[mi], h.x, h.y);
                    mma_bf16(acc[mi][ni], ahi[mi], l.x, l.y);
                    mma_bf16(acc[mi][ni], alo[mi], h.x, h.y);
                }
            }
        }

        // ---- Epilogue: C fragments -> GMEM (coalesced float2) ----
        float* ot = out + (size_t)tile * 16384;
        #pragma unroll
        for (int mi = 0; mi < 2; mi++) {
            int r0 = mgrp * 32 + mi * 16 + tq;
            #pragma unroll
            for (int ni = 0; ni < 8; ni++) {
                int c = ngrp * 64 + ni * 8 + tr * 2;
                *reinterpret_cast<float2*>(ot + r0 * 128 + c) =
                    make_float2(acc[mi][ni][0], acc[mi][ni][1]);
                *reinterpret_cast<float2*>(ot + (r0 + 8) * 128 + c) =
                    make_float2(acc[mi][ni][2], acc[mi][ni][3]);
            }
        }
    }
}

extern "C" void kernel_launch(void* const* d_in, const int* in_sizes, int n_in,
                              void* d_out, int out_size) {
    const float* x = (const float*)d_in[0];
    const float* rot = (const float*)d_in[1];
    float* out = (float*)d_out;

    int num_tiles = in_sizes[0] / 16384;  // 128x128 fp32 per tile

    static int num_sms = 0;
    if (num_sms == 0) {
        if (cudaDeviceGetAttribute(&num_sms, cudaDevAttrMultiProcessorCount, 0)
                != cudaSuccess || num_sms <= 0)
            num_sms = 148;
        cudaFuncSetAttribute(OrthogonalTransform_kernel,
                             cudaFuncAttributeMaxDynamicSharedMemorySize,
                             SMEM_BYTES);
    }

    int grid = 2 * num_sms;
    if (grid > num_tiles) grid = num_tiles;
    OrthogonalTransform_kernel<<<grid, THREADS, SMEM_BYTES>>>(x, rot, out,
                                                              num_tiles);
}

// round 5
// speedup vs baseline: 1.3117x; 1.3117x over previous
#include <cuda_runtime.h>
#include <cuda_fp16.h>
#include <cstdint>

// ============================================================================
// OrthogonalTransform: Y = X @ R, X viewed as (M=524288, 128), R 128x128.
// fp16 2-pass R-split HMMA: y = f16(x) * (Rhi + Rlo), fp32 accumulate.
// Persistent CTAs, 128x128 tiles, double-buffered A smem, coalesced LDG.128 ->
// swizzled fp16 smem -> ldmatrix.x4 fragments. B = R^T fragments packed in
// smem once per CTA (hi+lo, 16B/lane LDS.128 per (ks,nt)).
// Warp tile: 64 rows x 32 cols (4 m16 x 4 n8), 8 warps = 128x128.
// ============================================================================

#define THREADS 256
#define SMEM_A0 0
#define SMEM_A1 32768
#define SMEM_B  65536
#define SMEM_TOTAL (65536 + 65536)   // 2x32KB A bufs + 64KB B pack

__device__ __forceinline__ uint32_t smem_u32(const void* p) {
    uint32_t a;
    asm("{ .reg .u64 t; cvta.to.shared.u64 t, %1; cvt.u32.u64 %0, t; }"
        : "=r"(a) : "l"(p));
    return a;
}

__device__ __forceinline__ uint32_t h2u(__half2 h) {
    return *reinterpret_cast<uint32_t*>(&h);
}

// A-tile swizzle: row r holds 16 chunks of 16B; chunk j stored at
// (j&8) | ((j^r)&7). Conflict-free for row-major STS and 8-row ldmatrix.
__device__ __forceinline__ uint32_t swz(int row, int chunk) {
    return (uint32_t)((chunk & 8) | ((chunk ^ row) & 7));
}

__device__ __forceinline__ void mma_f16(float* d, const uint32_t* a,
                                        uint32_t b0, uint32_t b1) {
    asm volatile(
        "mma.sync.aligned.m16n8k16.row.col.f32.f16.f16.f32 "
        "{%0,%1,%2,%3}, {%4,%5,%6,%7}, {%8,%9}, {%0,%1,%2,%3};"
        : "+f"(d[0]), "+f"(d[1]), "+f"(d[2]), "+f"(d[3])
        : "r"(a[0]), "r"(a[1]), "r"(a[2]), "r"(a[3]), "r"(b0), "r"(b1));
}

__device__ __forceinline__ void ldmatrix4(uint32_t* a, uint32_t addr) {
    asm volatile(
        "ldmatrix.sync.aligned.m8n8.x4.shared.b16 {%0,%1,%2,%3}, [%4];"
        : "=r"(a[0]), "=r"(a[1]), "=r"(a[2]), "=r"(a[3]) : "r"(addr));
}

__global__ void __launch_bounds__(THREADS, 1)
OrthogonalTransform_kernel(const float* __restrict__ x,
                           const float* __restrict__ rot,
                           float* __restrict__ out,
                           int num_tiles) {
    extern __shared__ char smem[];
    const uint32_t smem_base = smem_u32(smem);
    const int tid = threadIdx.x;
    const int wid = tid >> 5;
    const int lane = tid & 31;
    const int mgrp = wid >> 2;        // 0..1 : rows mgrp*64 + mi*16
    const int ngrp = wid & 3;         // 0..3 : cols ngrp*32 + ni*8
    const int tq = lane >> 2;         // 0..7
    const int tr = lane & 3;          // 0..3

    // ---- Prologue 1: pack B = R fragments (hi+lo fp16) into smem ----
    // Entry (ks, nt, lane) : 16B = {bhi0, bhi1, blo0, blo1}.
    // Fragment: lane holds n = nt*8 + lane/4; k pairs (lane%4)*2 (+8) + ks*16.
    uint4* bp = reinterpret_cast<uint4*>(smem + SMEM_B);
    for (int e = tid; e < 4096; e += THREADS) {
        int le = e & 31;              // == lane (step 256 preserves low 5 bits)
        int nt = (e >> 5) & 15;
        int ks = e >> 9;
        int n  = nt * 8 + (le >> 2);
        int k0 = ks * 16 + (le & 3) * 2;
        float v00 = rot[k0 * 128 + n];
        float v01 = rot[(k0 + 1) * 128 + n];
        float v10 = rot[(k0 + 8) * 128 + n];
        float v11 = rot[(k0 + 9) * 128 + n];
        __half2 h0 = __floats2half2_rn(v00, v01);
        __half2 h1 = __floats2half2_rn(v10, v11);
        float2 f0 = __half22float2(h0);
        float2 f1 = __half22float2(h1);
        __half2 l0 = __floats2half2_rn(v00 - f0.x, v01 - f0.y);
        __half2 l1 = __floats2half2_rn(v10 - f1.x, v11 - f1.y);
        bp[e] = make_uint4(h2u(h0), h2u(h1), h2u(l0), h2u(l1));
    }

    // Per-thread A-staging constants: thread covers float4 f = i*256+tid,
    // i.e. row = i*8 + wid, chunk = lane/2, half = lane&1 (warp = one row / i).
    const int chunkA = lane >> 1;
    const int halfA  = lane & 1;

    int tile = blockIdx.x;
    if (tile >= num_tiles) return;

    // ---- Prologue 2: stage tile0 into A[0] ----
    {
        const float4* src = reinterpret_cast<const float4*>(x + (size_t)tile * 16384);
        #pragma unroll
        for (int i = 0; i < 16; i++) {
            float4 v = src[i * THREADS + tid];
            int row = i * 8 + wid;
            __half2 h01 = __floats2half2_rn(v.x, v.y);
            __half2 h23 = __floats2half2_rn(v.z, v.w);
            uint32_t off = (uint32_t)SMEM_A0 + row * 256
                         + (swz(row, chunkA) << 4) + (halfA << 3);
            *reinterpret_cast<uint2*>(smem + off) = make_uint2(h2u(h01), h2u(h23));
        }
    }
    __syncthreads();

    int it = 0;
    while (true) {
        const int buf = it & 1;
        const uint32_t Abase = smem_base + (buf ? SMEM_A1 : SMEM_A0);
        const int nxt = tile + gridDim.x;
        const bool has_next = nxt < num_tiles;

        // ---- Prefetch next tile into registers (overlaps with MMAs) ----
        float4 pf[16];
        if (has_next) {
            const float4* s2 =
                reinterpret_cast<const float4*>(x + (size_t)nxt * 16384);
            #pragma unroll
            for (int i = 0; i < 16; i++) pf[i] = s2[i * THREADS + tid];
        }

        // ---- Compute: 8 k-steps, 2-pass (hi+lo B) HMMA ----
        float acc[4][4][4];
        #pragma unroll
        for (int mi = 0; mi < 4; mi++)
            #pragma unroll
            for (int ni = 0; ni < 4; ni++)
                #pragma unroll
                for (int j = 0; j < 4; j++) acc[mi][ni][j] = 0.0f;

        const int g_roff = ((lane >> 3) & 1) << 3;  // 0 or 8
        const int g_coff = lane >> 4;               // 0 or 1 (k-chunk select)
        const int g_ri   = lane & 7;

        #pragma unroll
        for (int ks = 0; ks < 8; ks++) {
            uint32_t a[4][4];
            #pragma unroll
            for (int mi = 0; mi < 4; mi++) {
                int row = mgrp * 64 + mi * 16 + g_roff + g_ri;
                int chunk = 2 * ks + g_coff;
                uint32_t addr = Abase + row * 256 + (swz(row, chunk) << 4);
                ldmatrix4(a[mi], addr);
            }
            #pragma unroll
            for (int ni = 0; ni < 4; ni++) {
                uint4 b = bp[(ks * 16 + ngrp * 4 + ni) * 32 + lane];
                #pragma unroll
                for (int mi = 0; mi < 4; mi++) {
                    mma_f16(acc[mi][ni], a[mi], b.x, b.y);   // * Rhi
                    mma_f16(acc[mi][ni], a[mi], b.z, b.w);   // * Rlo
                }
            }
        }

        // ---- Commit prefetched tile into the other A buffer ----
        if (has_next) {
            uint32_t Aoff = buf ? SMEM_A0 : SMEM_A1;
            #pragma unroll
            for (int i = 0; i < 16; i++) {
                float4 v = pf[i];
                int row = i * 8 + wid;
                __half2 h01 = __floats2half2_rn(v.x, v.y);
                __half2 h23 = __floats2half2_rn(v.z, v.w);
                uint32_t off = Aoff + row * 256
                             + (swz(row, chunkA) << 4) + (halfA << 3);
                *reinterpret_cast<uint2*>(smem + off) =
                    make_uint2(h2u(h01), h2u(h23));
            }
        }

        // ---- Epilogue: C fragments -> GMEM ----
        float* ot = out + (size_t)tile * 16384;
        #pragma unroll
        for (int mi = 0; mi < 4; mi++) {
            int r0 = mgrp * 64 + mi * 16 + tq;
            #pragma unroll
            for (int ni = 0; ni < 4; ni++) {
                int c = ngrp * 32 + ni * 8 + tr * 2;
                *reinterpret_cast<float2*>(ot + r0 * 128 + c) =
                    make_float2(acc[mi][ni][0], acc[mi][ni][1]);
                *reinterpret_cast<float2*>(ot + (r0 + 8) * 128 + c) =
                    make_float2(acc[mi][ni][2], acc[mi][ni][3]);
            }
        }

        if (!has_next) break;
        __syncthreads();   // next A buffer fully staged, all reads of it done
        tile = nxt;
        it++;
    }
}

extern "C" void kernel_launch(void* const* d_in, const int* in_sizes, int n_in,
                              void* d_out, int out_size) {
    const float* x = (const float*)d_in[0];
    const float* rot = (const float*)d_in[1];
    float* out = (float*)d_out;

    int num_tiles = in_sizes[0] / 16384;  // 128x128 fp32 per tile

    static int num_sms = 0;
    if (num_sms == 0) {
        if (cudaDeviceGetAttribute(&num_sms, cudaDevAttrMultiProcessorCount, 0)
                != cudaSuccess || num_sms <= 0)
            num_sms = 148;
        cudaFuncSetAttribute(OrthogonalTransform_kernel,
                             cudaFuncAttributeMaxDynamicSharedMemorySize,
                             SMEM_TOTAL);
    }

    int grid = num_sms < num_tiles ? num_sms : num_tiles;
    OrthogonalTransform_kernel<<<grid, THREADS, SMEM_TOTAL>>>(x, rot, out,
                                                              num_tiles);
}

// round 7
// speedup vs baseline: 1.4868x; 1.1335x over previous
#include <cuda_runtime.h>
#include <cuda_fp16.h>
#include <cstdint>

// ============================================================================
// OrthogonalTransform: Y = X @ R, X viewed as (M=524288, 128), R 128x128.
// Single-pass fp16 HMMA: y = f16(x) * f16(R), fp32 accumulate.
// rel_err budget: ~3e-4 (measured 2.08e-4 with x-only rounding; R rounding
// adds the same magnitude in quadrature) vs 1e-3 threshold.
// Persistent CTAs, 2 CTAs/SM (<=128 regs via chunked prefetch), 128x128 tiles,
// double-buffered A smem, LDG.128 -> swizzled fp16 smem -> ldmatrix.x4.
// B = R^T fragments packed in smem once per CTA (fp16 hi only, 32KB).
// Warp tile: 64 rows x 32 cols (4 m16 x 4 n8), 8 warps = 128x128.
// ============================================================================

#define THREADS 256
#define SMEM_A0 0
#define SMEM_A1 32768
#define SMEM_B  65536
#define SMEM_TOTAL (65536 + 32768)   // 2x32KB A bufs + 32KB B pack

__device__ __forceinline__ uint32_t smem_u32(const void* p) {
    uint32_t a;
    asm("{ .reg .u64 t; cvta.to.shared.u64 t, %1; cvt.u32.u64 %0, t; }"
        : "=r"(a) : "l"(p));
    return a;
}

__device__ __forceinline__ uint32_t h2u(__half2 h) {
    return *reinterpret_cast<uint32_t*>(&h);
}

// A-tile swizzle: row r holds 16 chunks of 16B; chunk j stored at
// (j&8) | ((j^r)&7). Conflict-free for row-major STS and 8-row ldmatrix.
__device__ __forceinline__ uint32_t swz(int row, int chunk) {
    return (uint32_t)((chunk & 8) | ((chunk ^ row) & 7));
}

__device__ __forceinline__ void mma_f16(float* d, const uint32_t* a,
                                        uint32_t b0, uint32_t b1) {
    asm volatile(
        "mma.sync.aligned.m16n8k16.row.col.f32.f16.f16.f32 "
        "{%0,%1,%2,%3}, {%4,%5,%6,%7}, {%8,%9}, {%0,%1,%2,%3};"
        : "+f"(d[0]), "+f"(d[1]), "+f"(d[2]), "+f"(d[3])
        : "r"(a[0]), "r"(a[1]), "r"(a[2]), "r"(a[3]), "r"(b0), "r"(b1));
}

__device__ __forceinline__ void ldmatrix4(uint32_t* a, uint32_t addr) {
    asm volatile(
        "ldmatrix.sync.aligned.m8n8.x4.shared.b16 {%0,%1,%2,%3}, [%4];"
        : "=r"(a[0]), "=r"(a[1]), "=r"(a[2]), "=r"(a[3]) : "r"(addr));
}

__global__ void __launch_bounds__(THREADS, 2)
OrthogonalTransform_kernel(const float* __restrict__ x,
                           const float* __restrict__ rot,
                           float* __restrict__ out,
                           int num_tiles) {
    extern __shared__ char smem[];
    const uint32_t smem_base = smem_u32(smem);
    const int tid = threadIdx.x;
    const int wid = tid >> 5;
    const int lane = tid & 31;
    const int mgrp = wid >> 2;        // 0..1 : rows mgrp*64 + mi*16
    const int ngrp = wid & 3;         // 0..3 : cols ngrp*32 + ni*8
    const int tq = lane >> 2;         // 0..7
    const int tr = lane & 3;          // 0..3

    // ---- Prologue 1: pack B = R fragments (fp16) into smem ----
    // Entry (ks, nt, lane): uint2 = {b0 (k pair k0,k0+1), b1 (k0+8,k0+9)}.
    // Fragment (m16n8k16 col): lane holds n = nt*8 + lane/4, k0 = ks*16+(lane%4)*2.
    uint2* bp = reinterpret_cast<uint2*>(smem + SMEM_B);
    for (int e = tid; e < 4096; e += THREADS) {
        int le = e & 31;              // == lane (step 256 preserves low 5 bits)
        int nt = (e >> 5) & 15;
        int ks = e >> 9;
        int n  = nt * 8 + (le >> 2);
        int k0 = ks * 16 + (le & 3) * 2;
        __half2 h0 = __floats2half2_rn(rot[k0 * 128 + n], rot[(k0 + 1) * 128 + n]);
        __half2 h1 = __floats2half2_rn(rot[(k0 + 8) * 128 + n], rot[(k0 + 9) * 128 + n]);
        bp[e] = make_uint2(h2u(h0), h2u(h1));
    }

    // A staging: thread covers float4 f = i*256+tid -> row = i*8+wid,
    // chunk = lane/2, half = lane&1.
    const int chunkA = lane >> 1;
    const int halfA  = lane & 1;
    const uint32_t stsBase = (uint32_t)((lane >> 1) == chunkA ? 0 : 0)  // keep simple
                           + (swz(0, 0), 0u);  // (unused placeholder)

    int tile = blockIdx.x;
    if (tile >= num_tiles) return;

    // ---- Prologue 2: stage tile0 into A[0] ----
    {
        const float4* src = reinterpret_cast<const float4*>(x + (size_t)tile * 16384);
        #pragma unroll
        for (int i = 0; i < 16; i++) {
            float4 v = src[i * THREADS + tid];
            int row = i * 8 + wid;
            __half2 h01 = __floats2half2_rn(v.x, v.y);
            __half2 h23 = __floats2half2_rn(v.z, v.w);
            uint32_t off = (uint32_t)SMEM_A0 + row * 256
                         + (swz(row, chunkA) << 4) + (halfA << 3);
            *reinterpret_cast<uint2*>(smem + off) = make_uint2(h2u(h01), h2u(h23));
        }
    }
    __syncthreads();

    const int g_roff = ((lane >> 3) & 1) << 3;  // 0 or 8
    const int g_coff = lane >> 4;               // 0 or 1 (k-chunk select)
    const int g_ri   = lane & 7;

    int it = 0;
    while (true) {
        const int buf = it & 1;
        const uint32_t Abase = smem_base + (buf ? SMEM_A1 : SMEM_A0);
        const uint32_t Aother = buf ? (uint32_t)SMEM_A0 : (uint32_t)SMEM_A1;
        const int nxt = tile + gridDim.x;
        const bool has_next = nxt < num_tiles;
        const float4* s2 = reinterpret_cast<const float4*>(x + (size_t)nxt * 16384);

        float acc[4][4][4];
        #pragma unroll
        for (int mi = 0; mi < 4; mi++)
            #pragma unroll
            for (int ni = 0; ni < 4; ni++)
                #pragma unroll
                for (int j = 0; j < 4; j++) acc[mi][ni][j] = 0.0f;

        // Chunked prefetch: load chunk g (4x LDG.128) at ks=2g; commit chunk
        // g-1 to the spare A buffer at ks=2g (its readers finished at the
        // previous __syncthreads, so writing it any time this iter is safe).
        float4 pf[4];

        #pragma unroll
        for (int ks = 0; ks < 8; ks++) {
            if (has_next && (ks & 1) == 0) {
                int g = ks >> 1;
                if (g > 0) {
                    // commit chunk g-1
                    #pragma unroll
                    for (int j = 0; j < 4; j++) {
                        int i = (g - 1) * 4 + j;
                        int row = i * 8 + wid;
                        __half2 h01 = __floats2half2_rn(pf[j].x, pf[j].y);
                        __half2 h23 = __floats2half2_rn(pf[j].z, pf[j].w);
                        uint32_t off = Aother + row * 256
                                     + (swz(row, chunkA) << 4) + (halfA << 3);
                        *reinterpret_cast<uint2*>(smem + off) =
                            make_uint2(h2u(h01), h2u(h23));
                    }
                }
                // load chunk g
                #pragma unroll
                for (int j = 0; j < 4; j++)
                    pf[j] = s2[(g * 4 + j) * THREADS + tid];
            }

            uint32_t a[4][4];
            #pragma unroll
            for (int mi = 0; mi < 4; mi++) {
                int row = mgrp * 64 + mi * 16 + g_roff + g_ri;
                int chunk = 2 * ks + g_coff;
                uint32_t addr = Abase + row * 256 + (swz(row, chunk) << 4);
                ldmatrix4(a[mi], addr);
            }
            #pragma unroll
            for (int ni = 0; ni < 4; ni++) {
                uint2 b = bp[(ks * 16 + ngrp * 4 + ni) * 32 + lane];
                #pragma unroll
                for (int mi = 0; mi < 4; mi++)
                    mma_f16(acc[mi][ni], a[mi], b.x, b.y);
            }
        }

        // Commit last chunk
        if (has_next) {
            #pragma unroll
            for (int j = 0; j < 4; j++) {
                int i = 12 + j;
                int row = i * 8 + wid;
                __half2 h01 = __floats2half2_rn(pf[j].x, pf[j].y);
                __half2 h23 = __floats2half2_rn(pf[j].z, pf[j].w);
                uint32_t off = Aother + row * 256
                             + (swz(row, chunkA) << 4) + (halfA << 3);
                *reinterpret_cast<uint2*>(smem + off) =
                    make_uint2(h2u(h01), h2u(h23));
            }
        }

        // ---- Epilogue: C fragments -> GMEM ----
        float* ot = out + (size_t)tile * 16384;
        #pragma unroll
        for (int mi = 0; mi < 4; mi++) {
            int r0 = mgrp * 64 + mi * 16 + tq;
            #pragma unroll
            for (int ni = 0; ni < 4; ni++) {
                int c = ngrp * 32 + ni * 8 + tr * 2;
                *reinterpret_cast<float2*>(ot + r0 * 128 + c) =
                    make_float2(acc[mi][ni][0], acc[mi][ni][1]);
                *reinterpret_cast<float2*>(ot + (r0 + 8) * 128 + c) =
                    make_float2(acc[mi][ni][2], acc[mi][ni][3]);
            }
        }

        if (!has_next) break;
        __syncthreads();   // spare buffer fully staged; all reads of it done
        tile = nxt;
        it++;
    }
}

extern "C" void kernel_launch(void* const* d_in, const int* in_sizes, int n_in,
                              void* d_out, int out_size) {
    const float* x = (const float*)d_in[0];
    const float* rot = (const float*)d_in[1];
    float* out = (float*)d_out;

    int num_tiles = in_sizes[0] / 16384;  // 128x128 fp32 per tile

    static int num_sms = 0;
    if (num_sms == 0) {
        if (cudaDeviceGetAttribute(&num_sms, cudaDevAttrMultiProcessorCount, 0)
                != cudaSuccess || num_sms <= 0)
            num_sms = 148;
        cudaFuncSetAttribute(OrthogonalTransform_kernel,
                             cudaFuncAttributeMaxDynamicSharedMemorySize,
                             SMEM_TOTAL);
    }

    int grid = 2 * num_sms;
    if (grid > num_tiles) grid = num_tiles;
    OrthogonalTransform_kernel<<<grid, THREADS, SMEM_TOTAL>>>(x, rot, out,
                                                              num_tiles);
}

// round 10
// speedup vs baseline: 1.6191x; 1.0890x over previous
#include <cuda_runtime.h>
#include <cuda_fp16.h>
#include <cstdint>

// ============================================================================
// OrthogonalTransform: Y = X @ R, X viewed as (M=524288, 128), R 128x128.
// Single-pass fp16 HMMA, warp-specialized:
//   - 8 consumer warps: ldmatrix + mma + STG (never stall on GMEM loads)
//   - 4 producer warps: LDG.128 -> cvt fp16 -> STS (absorb all DRAM latency)
// CTA tile 64x128, warp tile 32x32. 3-deep A smem ring + named-barrier
// full/empty handshake. B = R fragments packed once (32KB). 2 CTAs/SM.
// ============================================================================

#define THREADS 384
#define NCONS 256              // consumer threads (warps 0-7)
#define ABUF_BYTES 16384       // 64 rows x 128 fp16 cols (256B/row)
#define SMEM_B (3 * ABUF_BYTES)
#define SMEM_TOTAL (SMEM_B + 32768)

__device__ __forceinline__ uint32_t smem_u32(const void* p) {
    uint32_t a;
    asm("{ .reg .u64 t; cvta.to.shared.u64 t, %1; cvt.u32.u64 %0, t; }"
        : "=r"(a) : "l"(p));
    return a;
}

__device__ __forceinline__ uint32_t h2u(__half2 h) {
    return *reinterpret_cast<uint32_t*>(&h);
}

// Row r holds 16 chunks of 16B; chunk j at (j&8) | ((j^r)&7).
// Conflict-free for row-major STS and 8-row ldmatrix.
__device__ __forceinline__ uint32_t swz(int row, int chunk) {
    return (uint32_t)((chunk & 8) | ((chunk ^ row) & 7));
}

__device__ __forceinline__ void mma_f16(float* d, const uint32_t* a,
                                        uint32_t b0, uint32_t b1) {
    asm volatile(
        "mma.sync.aligned.m16n8k16.row.col.f32.f16.f16.f32 "
        "{%0,%1,%2,%3}, {%4,%5,%6,%7}, {%8,%9}, {%0,%1,%2,%3};"
        : "+f"(d[0]), "+f"(d[1]), "+f"(d[2]), "+f"(d[3])
        : "r"(a[0]), "r"(a[1]), "r"(a[2]), "r"(a[3]), "r"(b0), "r"(b1));
}

__device__ __forceinline__ void ldmatrix4(uint32_t* a, uint32_t addr) {
    asm volatile(
        "ldmatrix.sync.aligned.m8n8.x4.shared.b16 {%0,%1,%2,%3}, [%4];"
        : "=r"(a[0]), "=r"(a[1]), "=r"(a[2]), "=r"(a[3]) : "r"(addr));
}

// full[s] = barrier 1+s (producers arrive, consumers sync)
// empty[s] = barrier 4+s (consumers arrive, producers sync)
__device__ __forceinline__ void bar_arrive(int id) {
    asm volatile("bar.arrive %0, %1;" :: "r"(id), "r"(THREADS) : "memory");
}
__device__ __forceinline__ void bar_wait(int id) {
    asm volatile("bar.sync %0, %1;" :: "r"(id), "r"(THREADS) : "memory");
}

__global__ void __launch_bounds__(THREADS, 2)
OrthogonalTransform_kernel(const float* __restrict__ x,
                           const float* __restrict__ rot,
                           float* __restrict__ out,
                           int num_tiles) {
    extern __shared__ char smem[];
    const uint32_t smem_base = smem_u32(smem);
    const int tid = threadIdx.x;

    // ---- Prologue: all 384 threads pack B = R fragments (fp16) ----
    // Entry (ks, nt, lane): uint2 = {k pair (k0,k0+1), (k0+8,k0+9)}.
    // Lane holds n = nt*8 + lane/4, k0 = ks*16 + (lane%4)*2.
    uint2* bp = reinterpret_cast<uint2*>(smem + SMEM_B);
    for (int e = tid; e < 4096; e += THREADS) {   // 384 = 12*32 keeps e&31==lane
        int le = e & 31;
        int nt = (e >> 5) & 15;
        int ks = e >> 9;
        int n  = nt * 8 + (le >> 2);
        int k0 = ks * 16 + (le & 3) * 2;
        __half2 h0 = __floats2half2_rn(rot[k0 * 128 + n], rot[(k0 + 1) * 128 + n]);
        __half2 h1 = __floats2half2_rn(rot[(k0 + 8) * 128 + n], rot[(k0 + 9) * 128 + n]);
        bp[e] = make_uint2(h2u(h0), h2u(h1));
    }
    __syncthreads();

    if (tid >= NCONS) {
        // ==================== PRODUCER (warps 8-11) ====================
        const int ptid = tid - NCONS;           // 0..127
        const int chunkA = (ptid & 31) >> 1;
        const int halfA  = ptid & 1;
        const int rbase  = ptid >> 5;           // row = i*4 + rbase

        int s = 0, it = 0;
        for (int tile = blockIdx.x; tile < num_tiles; tile += gridDim.x, ++it) {
            const float4* src =
                reinterpret_cast<const float4*>(x + (size_t)tile * 8192);
            // Issue first batch of LDGs BEFORE waiting (overlap with consumers)
            float4 pf[8];
            #pragma unroll
            for (int i = 0; i < 8; i++) pf[i] = src[i * 128 + ptid];

            if (it >= 3) bar_wait(4 + s);       // wait empty[s]

            const uint32_t Ab = (uint32_t)(s * ABUF_BYTES);
            // Commit batch 0 while batch 1 loads
            float4 pg[8];
            #pragma unroll
            for (int i = 0; i < 8; i++) pg[i] = src[(8 + i) * 128 + ptid];
            #pragma unroll
            for (int i = 0; i < 8; i++) {
                int row = i * 4 + rbase;
                __half2 h01 = __floats2half2_rn(pf[i].x, pf[i].y);
                __half2 h23 = __floats2half2_rn(pf[i].z, pf[i].w);
                uint32_t off = Ab + row * 256 + (swz(row, chunkA) << 4)
                             + (halfA << 3);
                *reinterpret_cast<uint2*>(smem + off) =
                    make_uint2(h2u(h01), h2u(h23));
            }
            #pragma unroll
            for (int i = 0; i < 8; i++) {
                int row = (8 + i) * 4 + rbase;
                __half2 h01 = __floats2half2_rn(pg[i].x, pg[i].y);
                __half2 h23 = __floats2half2_rn(pg[i].z, pg[i].w);
                uint32_t off = Ab + row * 256 + (swz(row, chunkA) << 4)
                             + (halfA << 3);
                *reinterpret_cast<uint2*>(smem + off) =
                    make_uint2(h2u(h01), h2u(h23));
            }
            asm volatile("membar.cta;" ::: "memory");
            bar_arrive(1 + s);                   // full[s]
            if (++s == 3) s = 0;
        }
    } else {
        // ==================== CONSUMER (warps 0-7) ====================
        const int wid = tid >> 5;
        const int lane = tid & 31;
        const int mgrp = wid >> 2;              // 0..1 : rows mgrp*32 + mi*16
        const int ngrp = wid & 3;               // 0..3 : cols ngrp*32 + ni*8
        const int tq = lane >> 2;
        const int tr = lane & 3;
        const int g_roff = ((lane >> 3) & 1) << 3;
        const int g_coff = lane >> 4;
        const int g_ri   = lane & 7;

        int s = 0;
        for (int tile = blockIdx.x; tile < num_tiles; tile += gridDim.x) {
            bar_wait(1 + s);                     // full[s]
            const uint32_t Abase = smem_base + (uint32_t)(s * ABUF_BYTES);

            float acc[2][4][4];
            #pragma unroll
            for (int mi = 0; mi < 2; mi++)
                #pragma unroll
                for (int ni = 0; ni < 4; ni++)
                    #pragma unroll
                    for (int j = 0; j < 4; j++) acc[mi][ni][j] = 0.0f;

            #pragma unroll
            for (int ks = 0; ks < 8; ks++) {
                uint32_t a[2][4];
                #pragma unroll
                for (int mi = 0; mi < 2; mi++) {
                    int row = mgrp * 32 + mi * 16 + g_roff + g_ri;
                    int chunk = 2 * ks + g_coff;
                    ldmatrix4(a[mi],
                              Abase + row * 256 + (swz(row, chunk) << 4));
                }
                #pragma unroll
                for (int ni = 0; ni < 4; ni++) {
                    uint2 b = bp[(ks * 16 + ngrp * 4 + ni) * 32 + lane];
                    #pragma unroll
                    for (int mi = 0; mi < 2; mi++)
                        mma_f16(acc[mi][ni], a[mi], b.x, b.y);
                }
            }

            // All smem reads of buf s are complete (their MMAs issued).
            bar_arrive(4 + s);                   // empty[s] — overlap epilogue
            if (++s == 3) s = 0;

            // ---- Epilogue: C fragments -> GMEM ----
            float* ot = out + (size_t)tile * 8192;
            #pragma unroll
            for (int mi = 0; mi < 2; mi++) {
                int r0 = mgrp * 32 + mi * 16 + tq;
                #pragma unroll
                for (int ni = 0; ni < 4; ni++) {
                    int c = ngrp * 32 + ni * 8 + tr * 2;
                    *reinterpret_cast<float2*>(ot + r0 * 128 + c) =
                        make_float2(acc[mi][ni][0], acc[mi][ni][1]);
                    *reinterpret_cast<float2*>(ot + (r0 + 8) * 128 + c) =
                        make_float2(acc[mi][ni][2], acc[mi][ni][3]);
                }
            }
        }
    }
}

extern "C" void kernel_launch(void* const* d_in, const int* in_sizes, int n_in,
                              void* d_out, int out_size) {
    const float* x = (const float*)d_in[0];
    const float* rot = (const float*)d_in[1];
    float* out = (float*)d_out;

    int num_tiles = in_sizes[0] / 8192;   // 64x128 fp32 per tile -> 8192

    static int num_sms = 0;
    if (num_sms == 0) {
        if (cudaDeviceGetAttribute(&num_sms, cudaDevAttrMultiProcessorCount, 0)
                != cudaSuccess || num_sms <= 0)
            num_sms = 148;
        cudaFuncSetAttribute(OrthogonalTransform_kernel,
                             cudaFuncAttributeMaxDynamicSharedMemorySize,
                             SMEM_TOTAL);
    }

    int grid = 2 * num_sms;
    if (grid > num_tiles) grid = num_tiles;
    OrthogonalTransform_kernel<<<grid, THREADS, SMEM_TOTAL>>>(x, rot, out,
                                                              num_tiles);
}